// round 12
// baseline (speedup 1.0000x reference)
#include <cuda_runtime.h>

#define NN 64
#define CC 128
#define TT 2048
#define SS 9
#define CT 2                // channels per warp
#define JW (CT + SS - 1)    // 10 contributing rows per warp
#define WPB 4               // warps per block
#define CPB (CT * WPB)      // 8 channels per block
#define TTILE 512           // t per block
#define KITER (TTILE / 32)  // 16
#define EPS 1e-5f

__device__ float g_sum[CC];
__device__ float g_sqs[CC];

__global__ __launch_bounds__(128)
void conv_stats_kernel(const float* __restrict__ x,
                       const float* __restrict__ w,
                       float* __restrict__ out) {
    // grid: (CC/CPB=16, TT/TTILE=4, NN=64), block 128
    const int warp = threadIdx.x >> 5;
    const int lane = threadIdx.x & 31;
    const int c0   = blockIdx.x * CPB + warp * CT;
    const int t0   = blockIdx.y * TTILE;
    const int n    = blockIdx.z;

    const float* xb = x + (size_t)n * CC * TT;

    // 10 shifted row pointers; invalid channels clamp to row 0 with sh=0
    // (their loads hit valid memory, contributions killed by zeroed weights).
    const float* ap[JW];
    int shv[JW];
    #pragma unroll
    for (int j = 0; j < JW; j++) {
        const int cc = c0 - (SS / 2) + j;
        if ((unsigned)cc < (unsigned)CC) {
            shv[j] = (cc % SS) - (SS / 2);               // [-4,4]
            ap[j]  = xb + cc * TT - shv[j];              // ap[j]+t = &x[cc, t-sh]
        } else {
            shv[j] = 0;
            ap[j]  = xb;                                 // harmless valid row
        }
    }

    // weights; zero any (dc,s) whose source row cc = c0-4+dc+s is invalid
    float wr[CT][SS];
    #pragma unroll
    for (int dc = 0; dc < CT; dc++)
        #pragma unroll
        for (int s = 0; s < SS; s++) {
            const int cc = c0 - (SS / 2) + dc + s;
            wr[dc][s] = ((unsigned)cc < (unsigned)CC)
                            ? __ldg(&w[(c0 + dc) * SS + s]) : 0.0f;
        }

    float* ob = out + ((size_t)n * CC + c0) * TT + t0;

    float ssum[CT], ssq[CT];
    #pragma unroll
    for (int dc = 0; dc < CT; dc++) { ssum[dc] = 0.0f; ssq[dc] = 0.0f; }

    const bool firstTile = (t0 == 0);
    const bool lastTile  = (t0 + TTILE == TT);

    #pragma unroll
    for (int k = 0; k < KITER; k++) {
        const int tl = k * 32 + lane;       // local t
        const int t  = t0 + tl;             // global t

        float xv[JW];
        // time-edge predication only needed at k==0 of first tile / k==KITER-1 of last
        if ((k == 0 && firstTile) || (k == KITER - 1 && lastTile)) {
            #pragma unroll
            for (int j = 0; j < JW; j++) {
                const int ti = t - shv[j];
                xv[j] = ((unsigned)ti < (unsigned)TT) ? __ldg(ap[j] + t) : 0.0f;
            }
        } else {
            #pragma unroll
            for (int j = 0; j < JW; j++)
                xv[j] = __ldg(ap[j] + t);    // LDG [Rj + imm]
        }

        float acc[CT];
        #pragma unroll
        for (int dc = 0; dc < CT; dc++) acc[dc] = 0.0f;
        #pragma unroll
        for (int j = 0; j < JW; j++) {
            #pragma unroll
            for (int dc = 0; dc < CT; dc++) {
                const int s = j - dc;
                if (s >= 0 && s < SS)
                    acc[dc] = fmaf(wr[dc][s], xv[j], acc[dc]);
            }
        }
        #pragma unroll
        for (int dc = 0; dc < CT; dc++) {
            ob[(size_t)dc * TT + tl] = acc[dc];
            ssum[dc] += acc[dc];
            ssq[dc]   = fmaf(acc[dc], acc[dc], ssq[dc]);
        }
    }

    // warp-exclusive channels: shuffle reduce + lane-0 atomics
    #pragma unroll
    for (int dc = 0; dc < CT; dc++) {
        float a = ssum[dc], b = ssq[dc];
        #pragma unroll
        for (int off = 16; off > 0; off >>= 1) {
            a += __shfl_xor_sync(0xFFFFFFFFu, a, off);
            b += __shfl_xor_sync(0xFFFFFFFFu, b, off);
        }
        if (lane == 0) {
            atomicAdd(&g_sum[c0 + dc], a);
            atomicAdd(&g_sqs[c0 + dc], b);
        }
    }
}

__global__ __launch_bounds__(512)
void normalize_kernel(float* __restrict__ out,
                      const float* __restrict__ gamma,
                      const float* __restrict__ beta) {
    // one block per (n, c) row; 512 threads x float4 = 2048 elements
    const int b = blockIdx.x;
    const int c = b & (CC - 1);
    const float invM = 1.0f / (float)((size_t)NN * TT);
    float m  = g_sum[c] * invM;
    float v  = g_sqs[c] * invM - m * m;
    float is = rsqrtf(v + EPS);
    float sc = __ldg(&gamma[c]) * is;
    float bi = __ldg(&beta[c]) - m * sc;

    float4* p = reinterpret_cast<float4*>(out + (size_t)b * TT);
    float4 v4 = p[threadIdx.x];
    v4.x = fmaxf(fmaf(v4.x, sc, bi), 0.0f);
    v4.y = fmaxf(fmaf(v4.y, sc, bi), 0.0f);
    v4.z = fmaxf(fmaf(v4.z, sc, bi), 0.0f);
    v4.w = fmaxf(fmaf(v4.w, sc, bi), 0.0f);
    p[threadIdx.x] = v4;
}

__global__ void zero_stats_kernel() {
    // runs LAST: leaves stats zeroed for the next graph replay
    // (__device__ globals are zero at module load, so replay 1 also sees zeros)
    int i = threadIdx.x;
    if (i < CC) { g_sum[i] = 0.0f; g_sqs[i] = 0.0f; }
}

extern "C" void kernel_launch(void* const* d_in, const int* in_sizes, int n_in,
                              void* d_out, int out_size) {
    const float* x     = (const float*)d_in[0];   // (64,128,2048) f32
    const float* cw    = (const float*)d_in[1];   // (128,9)       f32
    const float* gamma = (const float*)d_in[2];   // (128,)        f32
    const float* beta  = (const float*)d_in[3];   // (128,)        f32
    float* out = (float*)d_out;                   // (64,128,2048) f32

    dim3 grid(CC / CPB, TT / TTILE, NN);          // (16, 4, 64) = 4096 blocks
    conv_stats_kernel<<<grid, 128>>>(x, cw, out);
    normalize_kernel<<<NN * CC, 512>>>(out, gamma, beta);
    zero_stats_kernel<<<1, 128>>>();
}

// round 13
// speedup vs baseline: 1.2725x; 1.2725x over previous
#include <cuda_runtime.h>

#define NN 64
#define CC 128
#define TT 2048
#define SS 9
#define CT 4                // channels per warp
#define JW (CT + SS - 1)    // 12 contributing rows per warp
#define WPB 4               // warps per block
#define CPB (CT * WPB)      // 16 channels per block
#define TTILE 512           // t per block
#define KITER (TTILE / 32)  // 16
#define EPS 1e-5f

__device__ float g_sum[CC];
__device__ float g_sqs[CC];

__global__ __launch_bounds__(128)
void conv_stats_kernel(const float* __restrict__ x,
                       const float* __restrict__ w,
                       float* __restrict__ out) {
    // grid: (CC/CPB=8, TT/TTILE=4, NN=64), block 128
    const int warp = threadIdx.x >> 5;
    const int lane = threadIdx.x & 31;
    const int c0   = blockIdx.x * CPB + warp * CT;
    const int t0   = blockIdx.y * TTILE;
    const int n    = blockIdx.z;

    const float* xb = x + (size_t)n * CC * TT;

    // 12 shifted row pointers; invalid channels clamp to row 0 with sh=0
    // (their loads hit valid memory, contributions killed by zeroed weights).
    const float* ap[JW];
    int shv[JW];
    #pragma unroll
    for (int j = 0; j < JW; j++) {
        const int cc = c0 - (SS / 2) + j;
        if ((unsigned)cc < (unsigned)CC) {
            shv[j] = (cc % SS) - (SS / 2);               // [-4,4]
            ap[j]  = xb + cc * TT - shv[j];              // ap[j]+t = &x[cc, t-sh]
        } else {
            shv[j] = 0;
            ap[j]  = xb;                                 // harmless valid row
        }
    }

    // weights; zero any (dc,s) whose source row cc = c0-4+dc+s is invalid
    float wr[CT][SS];
    #pragma unroll
    for (int dc = 0; dc < CT; dc++)
        #pragma unroll
        for (int s = 0; s < SS; s++) {
            const int cc = c0 - (SS / 2) + dc + s;
            wr[dc][s] = ((unsigned)cc < (unsigned)CC)
                            ? __ldg(&w[(c0 + dc) * SS + s]) : 0.0f;
        }

    float* ob = out + ((size_t)n * CC + c0) * TT + t0;

    float ssum[CT], ssq[CT];
    #pragma unroll
    for (int dc = 0; dc < CT; dc++) { ssum[dc] = 0.0f; ssq[dc] = 0.0f; }

    const bool firstTile = (t0 == 0);
    const bool lastTile  = (t0 + TTILE == TT);

    // gather for slice k into dst[JW]; edge predication only at the two global ends
    #define GATHER(kk, dst)                                                       \
        do {                                                                      \
            const int _t = t0 + (kk) * 32 + lane;                                 \
            if (((kk) == 0 && firstTile) || ((kk) == KITER - 1 && lastTile)) {    \
                _Pragma("unroll")                                                 \
                for (int j = 0; j < JW; j++) {                                    \
                    const int ti = _t - shv[j];                                   \
                    dst[j] = ((unsigned)ti < (unsigned)TT) ? __ldg(ap[j] + _t)    \
                                                           : 0.0f;               \
                }                                                                 \
            } else {                                                              \
                _Pragma("unroll")                                                 \
                for (int j = 0; j < JW; j++)                                      \
                    dst[j] = __ldg(ap[j] + _t);   /* LDG [Rj + imm] */            \
            }                                                                     \
        } while (0)

    float xv[JW];
    GATHER(0, xv);                       // pipeline fill

    #pragma unroll
    for (int k = 0; k < KITER; k++) {
        float xn[JW];
        if (k + 1 < KITER) GATHER(k + 1, xn);   // prefetch next slice (overlaps compute)

        float acc[CT];
        #pragma unroll
        for (int dc = 0; dc < CT; dc++) acc[dc] = 0.0f;
        #pragma unroll
        for (int j = 0; j < JW; j++) {
            #pragma unroll
            for (int dc = 0; dc < CT; dc++) {
                const int s = j - dc;
                if (s >= 0 && s < SS)
                    acc[dc] = fmaf(wr[dc][s], xv[j], acc[dc]);
            }
        }
        const int tl = k * 32 + lane;
        #pragma unroll
        for (int dc = 0; dc < CT; dc++) {
            ob[(size_t)dc * TT + tl] = acc[dc];
            ssum[dc] += acc[dc];
            ssq[dc]   = fmaf(acc[dc], acc[dc], ssq[dc]);
        }

        #pragma unroll
        for (int j = 0; j < JW; j++) xv[j] = xn[j];   // renamed away by ptxas
    }
    #undef GATHER

    // warp-exclusive channels: shuffle reduce + lane-0 atomics
    #pragma unroll
    for (int dc = 0; dc < CT; dc++) {
        float a = ssum[dc], b = ssq[dc];
        #pragma unroll
        for (int off = 16; off > 0; off >>= 1) {
            a += __shfl_xor_sync(0xFFFFFFFFu, a, off);
            b += __shfl_xor_sync(0xFFFFFFFFu, b, off);
        }
        if (lane == 0) {
            atomicAdd(&g_sum[c0 + dc], a);
            atomicAdd(&g_sqs[c0 + dc], b);
        }
    }
}

__global__ __launch_bounds__(512)
void normalize_kernel(float* __restrict__ out,
                      const float* __restrict__ gamma,
                      const float* __restrict__ beta) {
    // one block per (n, c) row; 512 threads x float4 = 2048 elements
    const int b = blockIdx.x;
    const int c = b & (CC - 1);
    const float invM = 1.0f / (float)((size_t)NN * TT);
    float m  = g_sum[c] * invM;
    float v  = g_sqs[c] * invM - m * m;
    float is = rsqrtf(v + EPS);
    float sc = __ldg(&gamma[c]) * is;
    float bi = __ldg(&beta[c]) - m * sc;

    float4* p = reinterpret_cast<float4*>(out + (size_t)b * TT);
    float4 v4 = p[threadIdx.x];
    v4.x = fmaxf(fmaf(v4.x, sc, bi), 0.0f);
    v4.y = fmaxf(fmaf(v4.y, sc, bi), 0.0f);
    v4.z = fmaxf(fmaf(v4.z, sc, bi), 0.0f);
    v4.w = fmaxf(fmaf(v4.w, sc, bi), 0.0f);
    p[threadIdx.x] = v4;
}

__global__ void zero_stats_kernel() {
    // runs LAST: leaves stats zeroed for the next graph replay
    // (__device__ globals are zero at module load, so replay 1 also sees zeros)
    int i = threadIdx.x;
    if (i < CC) { g_sum[i] = 0.0f; g_sqs[i] = 0.0f; }
}

extern "C" void kernel_launch(void* const* d_in, const int* in_sizes, int n_in,
                              void* d_out, int out_size) {
    const float* x     = (const float*)d_in[0];   // (64,128,2048) f32
    const float* cw    = (const float*)d_in[1];   // (128,9)       f32
    const float* gamma = (const float*)d_in[2];   // (128,)        f32
    const float* beta  = (const float*)d_in[3];   // (128,)        f32
    float* out = (float*)d_out;                   // (64,128,2048) f32

    dim3 grid(CC / CPB, TT / TTILE, NN);          // (8, 4, 64) = 2048 blocks
    conv_stats_kernel<<<grid, 128>>>(x, cw, out);
    normalize_kernel<<<NN * CC, 512>>>(out, gamma, beta);
    zero_stats_kernel<<<1, 128>>>();
}